// round 2
// baseline (speedup 1.0000x reference)
#include <cuda_runtime.h>
#include <mma.h>
using namespace nvcuda;

// Problem constants
#define Bb 2
#define Tt 16
#define Hh 32
#define Ww 32
#define Cc 768
#define NHh 12
#define HDd 64
#define NTOK (Bb*Tt*Hh*Ww)      // 32768
#define F3 (3*Cc)               // 2304

// Scratch (no allocations allowed — device globals)
__device__ float g_y[NTOK * Cc];        // LN1 output, reused for LN2 output
__device__ float g_qkv[NTOK * F3];      // QKV GEMM output
__device__ float g_o[NTOK * Cc];        // attention output

// ---------------------------------------------------------------------------
// LayerNorm: one block (256 threads) per token, C=768 (3 elems per thread)
// ---------------------------------------------------------------------------
__global__ void ln_kernel(const float* __restrict__ x,
                          const float* __restrict__ w,
                          const float* __restrict__ b,
                          float* __restrict__ y) {
    int tok = blockIdx.x;
    const float* xr = x + (size_t)tok * Cc;
    float* yr = y + (size_t)tok * Cc;
    int t = threadIdx.x;

    float v0 = xr[t], v1 = xr[t + 256], v2 = xr[t + 512];
    float s  = v0 + v1 + v2;
    float ss = v0 * v0 + v1 * v1 + v2 * v2;

    __shared__ float reds[8], redss[8];
    #pragma unroll
    for (int o = 16; o; o >>= 1) {
        s  += __shfl_xor_sync(0xffffffffu, s,  o);
        ss += __shfl_xor_sync(0xffffffffu, ss, o);
    }
    int wid = t >> 5, lid = t & 31;
    if (lid == 0) { reds[wid] = s; redss[wid] = ss; }
    __syncthreads();
    if (t < 32) {
        s  = (lid < 8) ? reds[lid]  : 0.f;
        ss = (lid < 8) ? redss[lid] : 0.f;
        #pragma unroll
        for (int o = 4; o; o >>= 1) {
            s  += __shfl_xor_sync(0xffffffffu, s,  o);
            ss += __shfl_xor_sync(0xffffffffu, ss, o);
        }
        if (lid == 0) { reds[0] = s; redss[0] = ss; }
    }
    __syncthreads();
    float mu  = reds[0] * (1.0f / Cc);
    float var = redss[0] * (1.0f / Cc) - mu * mu;
    float rstd = rsqrtf(var + 1e-5f);

    yr[t]       = (v0 - mu) * rstd * w[t]       + b[t];
    yr[t + 256] = (v1 - mu) * rstd * w[t + 256] + b[t + 256];
    yr[t + 512] = (v2 - mu) * rstd * w[t + 512] + b[t + 512];
}

// ---------------------------------------------------------------------------
// TF32 GEMM:  C[m,n] = sum_k A[m,k] * Wt[n,k] + bias[n] (+ res[m,n])
// Tile: BM=128, BN=64, BK=32. 256 threads = 8 warps (4 m-dir x 2 n-dir),
// each warp does 32x32 via 2x2 wmma 16x16x8 tf32 fragments.
// ---------------------------------------------------------------------------
#define BM 128
#define BN 64
#define BK 32
#define LDA 40
#define LDB 40
#define LDC 68

template <bool RES>
__global__ void gemm_tf32(const float* __restrict__ A,
                          const float* __restrict__ Wt,
                          const float* __restrict__ bias,
                          const float* __restrict__ res,
                          float* __restrict__ Cout,
                          int M, int N, int K) {
    __shared__ float smem[BM * LDC];           // 8704 floats, reused for epilogue
    float* As = smem;                          // [BM][LDA] -> 5120 floats
    float* Bs = smem + BM * LDA;               // [BN][LDB] -> 2560 floats (7680 total)

    int tid = threadIdx.x;
    int m0 = blockIdx.y * BM;
    int n0 = blockIdx.x * BN;

    wmma::fragment<wmma::accumulator, 16, 16, 8, float> acc[2][2];
    #pragma unroll
    for (int i = 0; i < 2; i++)
        #pragma unroll
        for (int j = 0; j < 2; j++)
            wmma::fill_fragment(acc[i][j], 0.0f);

    int wid = tid >> 5;
    int wm = (wid & 3) * 32;       // warp m offset
    int wn = (wid >> 2) * 32;      // warp n offset

    for (int k0 = 0; k0 < K; k0 += BK) {
        // Load A tile 128x32 (16 elems/thread, coalesced along k)
        #pragma unroll
        for (int i = 0; i < (BM * BK) / 256; i++) {
            int idx = tid + i * 256;
            int r = idx >> 5, c = idx & 31;
            As[r * LDA + c] = wmma::__float_to_tf32(A[(size_t)(m0 + r) * K + k0 + c]);
        }
        // Load B tile 64x32 (8 elems/thread)
        #pragma unroll
        for (int i = 0; i < (BN * BK) / 256; i++) {
            int idx = tid + i * 256;
            int r = idx >> 5, c = idx & 31;
            Bs[r * LDB + c] = wmma::__float_to_tf32(Wt[(size_t)(n0 + r) * K + k0 + c]);
        }
        __syncthreads();

        #pragma unroll
        for (int kk = 0; kk < BK; kk += 8) {
            wmma::fragment<wmma::matrix_a, 16, 16, 8, wmma::precision::tf32, wmma::row_major> af[2];
            wmma::fragment<wmma::matrix_b, 16, 16, 8, wmma::precision::tf32, wmma::col_major> bf[2];
            #pragma unroll
            for (int i = 0; i < 2; i++)
                wmma::load_matrix_sync(af[i], &As[(wm + i * 16) * LDA + kk], LDA);
            #pragma unroll
            for (int j = 0; j < 2; j++)
                wmma::load_matrix_sync(bf[j], &Bs[(wn + j * 16) * LDB + kk], LDB);
            #pragma unroll
            for (int i = 0; i < 2; i++)
                #pragma unroll
                for (int j = 0; j < 2; j++)
                    wmma::mma_sync(acc[i][j], af[i], bf[j], acc[i][j]);
        }
        __syncthreads();
    }

    // Epilogue through shared (reuse smem)
    float* Cs = smem;
    #pragma unroll
    for (int i = 0; i < 2; i++)
        #pragma unroll
        for (int j = 0; j < 2; j++)
            wmma::store_matrix_sync(&Cs[(wm + i * 16) * LDC + wn + j * 16],
                                    acc[i][j], LDC, wmma::mem_row_major);
    __syncthreads();

    #pragma unroll
    for (int i = 0; i < (BM * BN) / 256; i++) {
        int idx = tid + i * 256;
        int r = idx >> 6, c = idx & 63;
        float v = Cs[r * LDC + c] + bias[n0 + c];
        size_t gidx = (size_t)(m0 + r) * N + n0 + c;
        if (RES) v += res[gidx];
        Cout[gidx] = v;
    }
}

// ---------------------------------------------------------------------------
// Attention over time axis: one warp per (b,h,w,head) unit. T=16, HD=64.
// q/k/v staged in padded smem (row stride 68 to break bank conflicts).
// ---------------------------------------------------------------------------
#define QSTR 68
__global__ void attn_kernel(const float* __restrict__ qkv, float* __restrict__ o) {
    int warp_in_blk = threadIdx.x >> 5;
    int lane = threadIdx.x & 31;
    int unit = blockIdx.x * 2 + warp_in_blk;   // 2 warps per block

    __shared__ float sm[2][3 * 16 * QSTR + 256];
    float* q = sm[warp_in_blk];
    float* k = q + 16 * QSTR;
    float* v = k + 16 * QSTR;
    float* p = v + 16 * QSTR;                  // 16x16 probs

    int head = unit % NHh;
    int s = unit / NHh;
    int w = s & 31; s >>= 5;
    int h = s & 31;
    int b = s >> 5;

    int spatial = h * 32 + w;
    int fofs = head * 192;

    // Load q,k,v (T=16 x HD=64 each)
    for (int idx = lane; idx < 16 * 64; idx += 32) {
        int t = idx >> 6, d = idx & 63;
        size_t g = (size_t)((b * 16 + t) * 1024 + spatial) * F3 + fofs + d;
        q[t * QSTR + d] = qkv[g];
        k[t * QSTR + d] = qkv[g + 64];
        v[t * QSTR + d] = qkv[g + 128];
    }
    __syncwarp();

    // Scores: lane pair (2 lanes per tq), each lane does 8 tk
    int tq = lane >> 1;
    int tk0 = (lane & 1) * 8;
    float sc[8];
    #pragma unroll
    for (int j = 0; j < 8; j++) {
        float acc = 0.f;
        #pragma unroll
        for (int d = 0; d < 64; d++)
            acc += q[tq * QSTR + d] * k[(tk0 + j) * QSTR + d];
        sc[j] = acc * 0.125f;   // 1/sqrt(64)
    }
    float m = sc[0];
    #pragma unroll
    for (int j = 1; j < 8; j++) m = fmaxf(m, sc[j]);
    m = fmaxf(m, __shfl_xor_sync(0xffffffffu, m, 1));
    float sum = 0.f;
    #pragma unroll
    for (int j = 0; j < 8; j++) { sc[j] = __expf(sc[j] - m); sum += sc[j]; }
    sum += __shfl_xor_sync(0xffffffffu, sum, 1);
    float inv = 1.0f / sum;
    #pragma unroll
    for (int j = 0; j < 8; j++) p[tq * 16 + tk0 + j] = sc[j] * inv;
    __syncwarp();

    // o[t,d] = sum_tk p[t,tk] * v[tk,d]
    for (int idx = lane; idx < 16 * 64; idx += 32) {
        int t = idx >> 6, d = idx & 63;
        float acc = 0.f;
        #pragma unroll
        for (int tk = 0; tk < 16; tk++)
            acc += p[t * 16 + tk] * v[tk * QSTR + d];
        size_t g = (size_t)((b * 16 + t) * 1024 + spatial) * Cc + head * 64 + d;
        o[g] = acc;
    }
}

// ---------------------------------------------------------------------------
// Launch
// ---------------------------------------------------------------------------
extern "C" void kernel_launch(void* const* d_in, const int* in_sizes, int n_in,
                              void* d_out, int out_size) {
    const float* x     = (const float*)d_in[0];
    const float* ln1_w = (const float*)d_in[1];
    const float* ln1_b = (const float*)d_in[2];
    const float* Wqkv  = (const float*)d_in[3];
    const float* bqkv  = (const float*)d_in[4];
    const float* ln2_w = (const float*)d_in[5];
    const float* ln2_b = (const float*)d_in[6];
    const float* Wout  = (const float*)d_in[7];
    const float* bout  = (const float*)d_in[8];
    float* out = (float*)d_out;

    static float *p_y = nullptr, *p_qkv = nullptr, *p_o = nullptr;
    if (!p_y) {
        cudaGetSymbolAddress((void**)&p_y, g_y);
        cudaGetSymbolAddress((void**)&p_qkv, g_qkv);
        cudaGetSymbolAddress((void**)&p_o, g_o);
    }

    // 1) LN1
    ln_kernel<<<NTOK, 256>>>(x, ln1_w, ln1_b, p_y);

    // 2) QKV GEMM: (32768 x 2304) = y(32768x768) @ Wqkv^T
    {
        dim3 grid(F3 / BN, NTOK / BM);
        gemm_tf32<false><<<grid, 256>>>(p_y, Wqkv, bqkv, nullptr, p_qkv,
                                        NTOK, F3, Cc);
    }

    // 3) Attention over time, per (b,h,w,head)
    {
        int nunits = Bb * Hh * Ww * NHh;     // 24576
        attn_kernel<<<nunits / 2, 64>>>(p_qkv, p_o);
    }

    // 4) LN2 (reuse g_y)
    ln_kernel<<<NTOK, 256>>>(p_o, ln2_w, ln2_b, p_y);

    // 5) Out GEMM + bias + residual
    {
        dim3 grid(Cc / BN, NTOK / BM);
        gemm_tf32<true><<<grid, 256>>>(p_y, Wout, bout, x, out,
                                       NTOK, Cc, Cc);
    }
}

// round 4
// speedup vs baseline: 1.0387x; 1.0387x over previous
#include <cuda_runtime.h>
#include <cstdint>
#include <mma.h>
using namespace nvcuda;

// Problem constants
#define Bb 2
#define Tt 16
#define Hh 32
#define Ww 32
#define Cc 768
#define NHh 12
#define HDd 64
#define NTOK (Bb*Tt*Hh*Ww)      // 32768
#define F3 (3*Cc)               // 2304

// Scratch (no allocations allowed — device globals)
__device__ float g_y[NTOK * Cc];        // LN1 output, reused for LN2 output
__device__ float g_qkv[NTOK * F3];      // QKV GEMM output
__device__ float g_o[NTOK * Cc];        // attention output

// ---------------------------------------------------------------------------
// LayerNorm: one block (192 threads) per token, C=768 (1 float4 per thread)
// ---------------------------------------------------------------------------
__global__ void ln_kernel(const float* __restrict__ x,
                          const float* __restrict__ w,
                          const float* __restrict__ b,
                          float* __restrict__ y) {
    int tok = blockIdx.x;
    int t = threadIdx.x;
    const float4* xr = (const float4*)(x + (size_t)tok * Cc);
    float4* yr = (float4*)(y + (size_t)tok * Cc);

    float4 v = xr[t];
    float s  = v.x + v.y + v.z + v.w;
    float ss = v.x*v.x + v.y*v.y + v.z*v.z + v.w*v.w;

    __shared__ float reds[6], redss[6];
    #pragma unroll
    for (int o = 16; o; o >>= 1) {
        s  += __shfl_xor_sync(0xffffffffu, s,  o);
        ss += __shfl_xor_sync(0xffffffffu, ss, o);
    }
    int wid = t >> 5, lid = t & 31;
    if (lid == 0) { reds[wid] = s; redss[wid] = ss; }
    __syncthreads();
    if (t < 32) {
        s  = (lid < 6) ? reds[lid]  : 0.f;
        ss = (lid < 6) ? redss[lid] : 0.f;
        #pragma unroll
        for (int o = 4; o; o >>= 1) {
            s  += __shfl_xor_sync(0xffffffffu, s,  o);
            ss += __shfl_xor_sync(0xffffffffu, ss, o);
        }
        if (lid == 0) { reds[0] = s; redss[0] = ss; }
    }
    __syncthreads();
    float mu  = reds[0] * (1.0f / Cc);
    float var = redss[0] * (1.0f / Cc) - mu * mu;
    float rstd = rsqrtf(var + 1e-5f);

    float4 wv = ((const float4*)w)[t];
    float4 bv = ((const float4*)b)[t];
    float4 r;
    r.x = (v.x - mu) * rstd * wv.x + bv.x;
    r.y = (v.y - mu) * rstd * wv.y + bv.y;
    r.z = (v.z - mu) * rstd * wv.z + bv.z;
    r.w = (v.w - mu) * rstd * wv.w + bv.w;
    yr[t] = r;
}

// ---------------------------------------------------------------------------
// TF32 GEMM with cp.async 2-stage pipeline.
// C[m,n] = sum_k A[m,k] * Wt[n,k] + bias[n] (+ res[m,n])
// BM=128, BN=64, BK=16. 256 threads = 8 warps (4 m x 2 n), warp tile 32x32.
// smem rows padded to 24 floats (96B, 16B-aligned) for cp.async.
// ---------------------------------------------------------------------------
#define BM 128
#define BN 64
#define BK 16
#define SSTR 24                 // smem row stride (floats)
#define LDC 68

__device__ __forceinline__ void cp_async16(float* smem_dst, const float* gmem_src) {
    unsigned int s = (unsigned int)__cvta_generic_to_shared(smem_dst);
    asm volatile("cp.async.cg.shared.global [%0], [%1], 16;\n" :: "r"(s), "l"(gmem_src));
}
#define CP_COMMIT() asm volatile("cp.async.commit_group;\n" ::: "memory")
#define CP_WAIT1()  asm volatile("cp.async.wait_group 1;\n" ::: "memory")
#define CP_WAIT0()  asm volatile("cp.async.wait_group 0;\n" ::: "memory")

template <bool RES>
__global__ __launch_bounds__(256) void gemm_tf32(
        const float* __restrict__ A,
        const float* __restrict__ Wt,
        const float* __restrict__ bias,
        const float* __restrict__ res,
        float* __restrict__ Cout,
        int M, int N, int K) {
    // smem: As[2][128*24]=6144, Bs[2][64*24]=3072 -> 9216 floats (36.9KB)
    __shared__ __align__(16) float smem[9216];
    float* As[2] = { smem,        smem + 3072 };
    float* Bs[2] = { smem + 6144, smem + 7680 };

    int tid = threadIdx.x;
    int m0 = blockIdx.y * BM;
    int n0 = blockIdx.x * BN;

    // cp.async mapping: row = tid>>2, col4 = tid&3 (4 float4 per 16-float row)
    int lrow = tid >> 2;
    int lc4  = (tid & 3) * 4;

    const float* Abase = A  + (size_t)(m0 + lrow) * K + lc4;
    const float* Bbase = Wt + (size_t)(n0 + lrow) * K + lc4;

    int wid = tid >> 5;
    int wm = (wid & 3) * 32;
    int wn = (wid >> 2) * 32;

    wmma::fragment<wmma::accumulator, 16, 16, 8, float> acc[2][2];
    #pragma unroll
    for (int i = 0; i < 2; i++)
        #pragma unroll
        for (int j = 0; j < 2; j++)
            wmma::fill_fragment(acc[i][j], 0.0f);

    int nit = K / BK;

    // Prologue: stage 0
    {
        cp_async16(&As[0][lrow * SSTR + lc4],        Abase);
        cp_async16(&As[0][(lrow + 64) * SSTR + lc4], Abase + (size_t)64 * K);
        cp_async16(&Bs[0][lrow * SSTR + lc4],        Bbase);
        CP_COMMIT();
    }

    for (int it = 0; it < nit; it++) {
        if (it + 1 < nit) {
            int ko = (it + 1) * BK;
            int st = (it + 1) & 1;
            cp_async16(&As[st][lrow * SSTR + lc4],        Abase + ko);
            cp_async16(&As[st][(lrow + 64) * SSTR + lc4], Abase + (size_t)64 * K + ko);
            cp_async16(&Bs[st][lrow * SSTR + lc4],        Bbase + ko);
            CP_COMMIT();
            CP_WAIT1();
        } else {
            CP_WAIT0();
        }
        __syncthreads();

        int cur = it & 1;
        #pragma unroll
        for (int kk = 0; kk < BK; kk += 8) {
            wmma::fragment<wmma::matrix_a, 16, 16, 8, wmma::precision::tf32, wmma::row_major> af[2];
            wmma::fragment<wmma::matrix_b, 16, 16, 8, wmma::precision::tf32, wmma::col_major> bf[2];
            #pragma unroll
            for (int i = 0; i < 2; i++) {
                wmma::load_matrix_sync(af[i], &As[cur][(wm + i * 16) * SSTR + kk], SSTR);
                #pragma unroll
                for (int e = 0; e < af[i].num_elements; e++)
                    af[i].x[e] = wmma::__float_to_tf32(af[i].x[e]);
            }
            #pragma unroll
            for (int j = 0; j < 2; j++) {
                wmma::load_matrix_sync(bf[j], &Bs[cur][(wn + j * 16) * SSTR + kk], SSTR);
                #pragma unroll
                for (int e = 0; e < bf[j].num_elements; e++)
                    bf[j].x[e] = wmma::__float_to_tf32(bf[j].x[e]);
            }
            #pragma unroll
            for (int i = 0; i < 2; i++)
                #pragma unroll
                for (int j = 0; j < 2; j++)
                    wmma::mma_sync(acc[i][j], af[i], bf[j], acc[i][j]);
        }
        __syncthreads();
    }

    // Epilogue through shared (reuse smem; 128*68=8704 <= 9216)
    float* Cs = smem;
    #pragma unroll
    for (int i = 0; i < 2; i++)
        #pragma unroll
        for (int j = 0; j < 2; j++)
            wmma::store_matrix_sync(&Cs[(wm + i * 16) * LDC + wn + j * 16],
                                    acc[i][j], LDC, wmma::mem_row_major);
    __syncthreads();

    #pragma unroll
    for (int i = 0; i < (BM * BN) / 256; i++) {
        int idx = tid + i * 256;
        int r = idx >> 6, c = idx & 63;
        float v = Cs[r * LDC + c] + bias[n0 + c];
        size_t gidx = (size_t)(m0 + r) * N + n0 + c;
        if (RES) v += res[gidx];
        Cout[gidx] = v;
    }
}

// ---------------------------------------------------------------------------
// Attention over time axis: one warp per (b,h,w,head) unit. T=16, HD=64.
// ---------------------------------------------------------------------------
#define QSTR 68
__global__ void attn_kernel(const float* __restrict__ qkv, float* __restrict__ o) {
    int warp_in_blk = threadIdx.x >> 5;
    int lane = threadIdx.x & 31;
    int unit = blockIdx.x * 2 + warp_in_blk;   // 2 warps per block

    __shared__ float sm[2][3 * 16 * QSTR + 256];
    float* q = sm[warp_in_blk];
    float* k = q + 16 * QSTR;
    float* v = k + 16 * QSTR;
    float* p = v + 16 * QSTR;                  // 16x16 probs

    int head = unit % NHh;
    int s = unit / NHh;
    int w = s & 31; s >>= 5;
    int h = s & 31;
    int b = s >> 5;

    int spatial = h * 32 + w;
    int fofs = head * 192;

    // Load q,k,v (T=16 x HD=64 each)
    for (int idx = lane; idx < 16 * 64; idx += 32) {
        int t = idx >> 6, d = idx & 63;
        size_t g = (size_t)((b * 16 + t) * 1024 + spatial) * F3 + fofs + d;
        q[t * QSTR + d] = qkv[g];
        k[t * QSTR + d] = qkv[g + 64];
        v[t * QSTR + d] = qkv[g + 128];
    }
    __syncwarp();

    // Scores: lane pair (2 lanes per tq), each lane does 8 tk
    int tq = lane >> 1;
    int tk0 = (lane & 1) * 8;
    float sc[8];
    #pragma unroll
    for (int j = 0; j < 8; j++) {
        float acc = 0.f;
        #pragma unroll
        for (int d = 0; d < 64; d++)
            acc += q[tq * QSTR + d] * k[(tk0 + j) * QSTR + d];
        sc[j] = acc * 0.125f;   // 1/sqrt(64)
    }
    float m = sc[0];
    #pragma unroll
    for (int j = 1; j < 8; j++) m = fmaxf(m, sc[j]);
    m = fmaxf(m, __shfl_xor_sync(0xffffffffu, m, 1));
    float sum = 0.f;
    #pragma unroll
    for (int j = 0; j < 8; j++) { sc[j] = __expf(sc[j] - m); sum += sc[j]; }
    sum += __shfl_xor_sync(0xffffffffu, sum, 1);
    float inv = 1.0f / sum;
    #pragma unroll
    for (int j = 0; j < 8; j++) p[tq * 16 + tk0 + j] = sc[j] * inv;
    __syncwarp();

    // o[t,d] = sum_tk p[t,tk] * v[tk,d]
    for (int idx = lane; idx < 16 * 64; idx += 32) {
        int t = idx >> 6, d = idx & 63;
        float acc = 0.f;
        #pragma unroll
        for (int tk = 0; tk < 16; tk++)
            acc += p[t * 16 + tk] * v[tk * QSTR + d];
        size_t g = (size_t)((b * 16 + t) * 1024 + spatial) * Cc + head * 64 + d;
        o[g] = acc;
    }
}

// ---------------------------------------------------------------------------
// Launch
// ---------------------------------------------------------------------------
extern "C" void kernel_launch(void* const* d_in, const int* in_sizes, int n_in,
                              void* d_out, int out_size) {
    const float* x     = (const float*)d_in[0];
    const float* ln1_w = (const float*)d_in[1];
    const float* ln1_b = (const float*)d_in[2];
    const float* Wqkv  = (const float*)d_in[3];
    const float* bqkv  = (const float*)d_in[4];
    const float* ln2_w = (const float*)d_in[5];
    const float* ln2_b = (const float*)d_in[6];
    const float* Wout  = (const float*)d_in[7];
    const float* bout  = (const float*)d_in[8];
    float* out = (float*)d_out;

    static float *p_y = nullptr, *p_qkv = nullptr, *p_o = nullptr;
    if (!p_y) {
        cudaGetSymbolAddress((void**)&p_y, g_y);
        cudaGetSymbolAddress((void**)&p_qkv, g_qkv);
        cudaGetSymbolAddress((void**)&p_o, g_o);
    }

    // 1) LN1
    ln_kernel<<<NTOK, 192>>>(x, ln1_w, ln1_b, p_y);

    // 2) QKV GEMM: (32768 x 2304) = y(32768x768) @ Wqkv^T
    {
        dim3 grid(F3 / BN, NTOK / BM);
        gemm_tf32<false><<<grid, 256>>>(p_y, Wqkv, bqkv, nullptr, p_qkv,
                                        NTOK, F3, Cc);
    }

    // 3) Attention over time, per (b,h,w,head)
    {
        int nunits = Bb * Hh * Ww * NHh;     // 24576
        attn_kernel<<<nunits / 2, 64>>>(p_qkv, p_o);
    }

    // 4) LN2 (reuse g_y)
    ln_kernel<<<NTOK, 192>>>(p_o, ln2_w, ln2_b, p_y);

    // 5) Out GEMM + bias + residual
    {
        dim3 grid(Cc / BN, NTOK / BM);
        gemm_tf32<true><<<grid, 256>>>(p_y, Wout, bout, x, out,
                                       NTOK, Cc, Cc);
    }
}